// round 7
// baseline (speedup 1.0000x reference)
#include <cuda_runtime.h>
#include <cuda_fp16.h>
#include <cstdint>
#include <math.h>

#define N_NODES   65536
#define HIDDEN    256
#define NUM_GRAPHS 64
#define VOCAB     50000
#define LAYERS    3
#define MAX_E     1114112
#define NEG_SLOPE 0.2f
#define EPS_SM    1e-16f

// ---------------- scratch ----------------
__device__ __half g_x[N_NODES * HIDDEN];
__device__ __half g_h[N_NODES * HIDDEN];
__device__ __half g_t[N_NODES * HIDDEN];
__device__ __half g_WT[LAYERS * HIDDEN * HIDDEN];
__device__ float g_Wc[2 * HIDDEN * HIDDEN];
__device__ float g_bc[2 * HIDDEN];
__device__ float g_es[N_NODES];
__device__ float g_ed[N_NODES];
__device__ int   g_deg[N_NODES];
__device__ int   g_off[N_NODES + 1];
__device__ int   g_cur[N_NODES];
__device__ int   g_csr[MAX_E];
__device__ float g_pool[NUM_GRAPHS * HIDDEN];
__device__ float g_small[NUM_GRAPHS * HIDDEN];
__device__ int   g_gcnt[NUM_GRAPHS];

__device__ __forceinline__ void mma_f16(float* c, const uint32_t* a,
                                        uint32_t b0, uint32_t b1) {
    asm volatile(
        "mma.sync.aligned.m16n8k16.row.col.f32.f16.f16.f32 "
        "{%0,%1,%2,%3}, {%4,%5,%6,%7}, {%8,%9}, {%0,%1,%2,%3};\n"
        : "+f"(c[0]), "+f"(c[1]), "+f"(c[2]), "+f"(c[3])
        : "r"(a[0]), "r"(a[1]), "r"(a[2]), "r"(a[3]), "r"(b0), "r"(b1));
}

// ---------------- kernel 1: embedding gather + deg init ----------------
__global__ void k_embed(const int* __restrict__ nodes, const float* __restrict__ emb) {
    int idx = blockIdx.x * blockDim.x + threadIdx.x;
    if (idx < N_NODES) g_deg[idx] = 1;     // self loop
    if (idx < N_NODES * HIDDEN) {
        int n = idx >> 8;
        int c = idx & 255;
        g_x[idx] = __float2half(emb[(size_t)nodes[n] * HIDDEN + c]);
    }
}

// ---------------- kernel 2: compose Wc_l = Wl_l @ Wg_{l+1} (both layers) --------
#define BM 64
#define BN 64
#define BK 16
__global__ void k_compose(const float* __restrict__ Wl, const float* __restrict__ Wg) {
    __shared__ float As[BM][BK];
    __shared__ float Bs[BK][BN + 1];
    const float* A = Wl + blockIdx.z * HIDDEN * HIDDEN;
    const float* B = Wg + (blockIdx.z + 1) * HIDDEN * HIDDEN;
    float* C = g_Wc + blockIdx.z * HIDDEN * HIDDEN;
    int tid = threadIdx.y * 16 + threadIdx.x;
    int m0 = blockIdx.y * BM, n0 = blockIdx.x * BN;
    float acc[4][4] = {};
    for (int k0 = 0; k0 < HIDDEN; k0 += BK) {
#pragma unroll
        for (int r = 0; r < 4; r++) {
            int e = tid + r * 256;
            int m = e / BK, k = e % BK;
            As[m][k] = A[(size_t)(m0 + m) * HIDDEN + k0 + k];
        }
#pragma unroll
        for (int r = 0; r < 4; r++) {
            int e = tid + r * 256;
            int k = e / BN, n = e % BN;
            Bs[k][n] = B[(size_t)(k0 + k) * HIDDEN + n0 + n];
        }
        __syncthreads();
#pragma unroll
        for (int kk = 0; kk < BK; kk++) {
            float ra[4], rb[4];
#pragma unroll
            for (int i = 0; i < 4; i++) ra[i] = As[threadIdx.y * 4 + i][kk];
#pragma unroll
            for (int j = 0; j < 4; j++) rb[j] = Bs[kk][threadIdx.x * 4 + j];
#pragma unroll
            for (int i = 0; i < 4; i++)
#pragma unroll
                for (int j = 0; j < 4; j++) acc[i][j] += ra[i] * rb[j];
        }
        __syncthreads();
    }
#pragma unroll
    for (int i = 0; i < 4; i++)
#pragma unroll
        for (int j = 0; j < 4; j++)
            C[(size_t)(m0 + threadIdx.y * 4 + i) * HIDDEN + n0 + threadIdx.x * 4 + j] =
                acc[i][j];
}

// ---------------- kernel 3: transposes + composed bias ----------------
// blocks [0,256): WT slot0 from Wg[0]; [256,768): slots 1,2 from g_Wc; [768,770): bias
__global__ void k_prep(const float* __restrict__ Wg, const float* __restrict__ bl) {
    int b = blockIdx.x;
    if (b < 256) {
        int i = b * 256 + threadIdx.x;
        int n = i >> 8, k = i & 255;
        g_WT[i] = __float2half(Wg[k * HIDDEN + n]);
    } else if (b < 768) {
        int i = (b - 256) * 256 + threadIdx.x;          // 0..131071
        int which = i >> 16;
        int nk = i & 65535;
        int n = nk >> 8, k = nk & 255;
        g_WT[(1 + which) * HIDDEN * HIDDEN + nk] =
            __float2half(g_Wc[which * HIDDEN * HIDDEN + k * HIDDEN + n]);
    } else {
        int which = b - 768;
        int n = threadIdx.x;
        const float* bb = bl + which * HIDDEN;
        const float* W = Wg + (which + 1) * HIDDEN * HIDDEN;
        float s = 0.f;
        for (int k = 0; k < HIDDEN; k++) s += bb[k] * W[k * HIDDEN + n];
        g_bc[which * HIDDEN + n] = s;
    }
}

// ============ kernel 4 (PROFILED): fp16 mma GEMM ============
#define STG_W 6144
#define RED_W 12288
#define SMEM_MMA (RED_W * 4 + 1024)

struct StageRegs { uint4 a, b0, b1; };

__device__ __forceinline__ void stage_ldg(StageRegs& R, const __half* __restrict__ A,
                                          const __half* __restrict__ BT,
                                          int m0, int kb, int t) {
    {
        int row = t >> 2, j = t & 3;
        R.a = *(const uint4*)(A + (size_t)(m0 + row) * HIDDEN + kb * 32 + j * 8);
    }
#pragma unroll
    for (int i = 0; i < 2; i++) {
        int f = t + 512 * i;
        int n = f >> 2, j = f & 3;
        uint4 v = *(const uint4*)(BT + (size_t)n * HIDDEN + kb * 32 + j * 8);
        if (i == 0) R.b0 = v; else R.b1 = v;
    }
}

__device__ __forceinline__ void stage_sts(const StageRegs& R, uint32_t* __restrict__ buf,
                                          int t) {
    {
        int row = t >> 2, j = t & 3;
        int mt = row >> 4, mr = row & 15, g = mr & 7;
        int ks = j >> 1, reg = (mr >> 3) + 2 * (j & 1);
        uint32_t wb = ((mt * 2 + ks) * 32 + g * 4) * 4 + reg;
        buf[wb] = R.a.x; buf[wb + 4] = R.a.y; buf[wb + 8] = R.a.z; buf[wb + 12] = R.a.w;
    }
#pragma unroll
    for (int i = 0; i < 2; i++) {
        int f = t + 512 * i;
        int n = f >> 2, j = f & 3;
        int nt = n >> 3, g = n & 7;
        int ks = j >> 1, reg = j & 1;
        uint4 v = (i == 0) ? R.b0 : R.b1;
        uint32_t wb = 2048 + ((nt * 2 + ks) * 32 + g * 4) * 2 + reg;
        buf[wb] = v.x; buf[wb + 2] = v.y; buf[wb + 4] = v.z; buf[wb + 6] = v.w;
    }
}

__global__ void __launch_bounds__(512, 1) k_gemm_mma(
    const __half* __restrict__ A, const __half* __restrict__ BT,
    __half* __restrict__ C, const float* __restrict__ bias,
    const float* __restrict__ avS, const float* __restrict__ avD,
    float* __restrict__ es, float* __restrict__ ed)
{
    extern __shared__ uint32_t smw[];
    float* red = (float*)(smw + RED_W);
    const int t = threadIdx.x;
    const int lane = t & 31, wid = t >> 5;
    const int wm = wid & 3, wn = wid >> 2;
    const int m0 = blockIdx.x * 128;
    const int g = lane >> 2, tig = lane & 3;

    if (t < 256) red[t] = 0.f;

    float acc[2][8][4];
#pragma unroll
    for (int i = 0; i < 2; i++)
#pragma unroll
        for (int j = 0; j < 8; j++)
#pragma unroll
            for (int k = 0; k < 4; k++) acc[i][j][k] = 0.f;

    StageRegs R;
    stage_ldg(R, A, BT, m0, 0, t);
    stage_sts(R, smw, t);
    __syncthreads();

#pragma unroll 1
    for (int kb = 0; kb < 8; kb++) {
        const uint32_t* buf = smw + (kb & 1) * STG_W;
        if (kb < 7) stage_ldg(R, A, BT, m0, kb + 1, t);
#pragma unroll
        for (int ks = 0; ks < 2; ks++) {
            uint4 av[2];
#pragma unroll
            for (int mi = 0; mi < 2; mi++) {
                int mt = wm * 2 + mi;
                av[mi] = *(const uint4*)&buf[((mt * 2 + ks) * 32 + lane) * 4];
            }
#pragma unroll
            for (int nt8 = 0; nt8 < 8; nt8++) {
                int nt = wn * 8 + nt8;
                uint2 bv = *(const uint2*)&buf[2048 + ((nt * 2 + ks) * 32 + lane) * 2];
                mma_f16(acc[0][nt8], (const uint32_t*)&av[0], bv.x, bv.y);
                mma_f16(acc[1][nt8], (const uint32_t*)&av[1], bv.x, bv.y);
            }
        }
        if (kb < 7) {
            stage_sts(R, smw + ((kb + 1) & 1) * STG_W, t);
            __syncthreads();
        }
    }

    float esp[2][2] = {{0.f, 0.f}, {0.f, 0.f}};
    float edp[2][2] = {{0.f, 0.f}, {0.f, 0.f}};
#pragma unroll
    for (int mi = 0; mi < 2; mi++) {
        int row = m0 + wm * 32 + mi * 16 + g;
#pragma unroll
        for (int nt8 = 0; nt8 < 8; nt8++) {
            int col = wn * 64 + nt8 * 8 + tig * 2;
            float a0 = acc[mi][nt8][0], a1 = acc[mi][nt8][1];
            float a2 = acc[mi][nt8][2], a3 = acc[mi][nt8][3];
            if (bias) {
                float b0 = __ldg(bias + col), b1 = __ldg(bias + col + 1);
                a0 += b0; a1 += b1; a2 += b0; a3 += b1;
            }
            *(__half2*)(C + (size_t)row * HIDDEN + col) = __floats2half2_rn(a0, a1);
            *(__half2*)(C + (size_t)(row + 8) * HIDDEN + col) = __floats2half2_rn(a2, a3);
            float s0 = __ldg(avS + col), s1 = __ldg(avS + col + 1);
            float d0 = __ldg(avD + col), d1 = __ldg(avD + col + 1);
            esp[mi][0] += a0 * s0 + a1 * s1;
            esp[mi][1] += a2 * s0 + a3 * s1;
            edp[mi][0] += a0 * d0 + a1 * d1;
            edp[mi][1] += a2 * d0 + a3 * d1;
        }
    }
#pragma unroll
    for (int o = 1; o <= 2; o <<= 1) {
#pragma unroll
        for (int mi = 0; mi < 2; mi++)
#pragma unroll
            for (int hv = 0; hv < 2; hv++) {
                esp[mi][hv] += __shfl_xor_sync(0xffffffffu, esp[mi][hv], o);
                edp[mi][hv] += __shfl_xor_sync(0xffffffffu, edp[mi][hv], o);
            }
    }
    if (tig == 0) {
#pragma unroll
        for (int mi = 0; mi < 2; mi++)
#pragma unroll
            for (int hv = 0; hv < 2; hv++) {
                int rl = wm * 32 + mi * 16 + hv * 8 + g;
                atomicAdd(&red[rl], esp[mi][hv]);
                atomicAdd(&red[128 + rl], edp[mi][hv]);
            }
    }
    __syncthreads();
    if (t < 128) {
        es[m0 + t] = red[t];
        ed[m0 + t] = red[128 + t];
    }
}

// ---------------- CSR build ----------------
__global__ void k_count_deg(const int* __restrict__ dst, int E) {
    int e = blockIdx.x * blockDim.x + threadIdx.x;
    if (e < E) atomicAdd(&g_deg[dst[e]], 1);
}
// scan + init_cur fused
__global__ void k_scan() {
    __shared__ int sh[1024];
    int t = threadIdx.x;
    int base = t * 64;
    int s = 0;
    for (int j = 0; j < 64; j++) s += g_deg[base + j];
    sh[t] = s;
    __syncthreads();
    for (int d = 1; d < 1024; d <<= 1) {
        int v = (t >= d) ? sh[t - d] : 0;
        __syncthreads();
        sh[t] += v;
        __syncthreads();
    }
    int run = sh[t] - s;
    for (int j = 0; j < 64; j++) {
        g_off[base + j] = run;
        g_cur[base + j] = run;
        run += g_deg[base + j];
    }
    if (t == 1023) g_off[N_NODES] = run;
}
// fill + selfloop fused (selfloop slot is the last, never touched by fill)
__global__ void k_fill(const int* __restrict__ src, const int* __restrict__ dst, int E) {
    int e = blockIdx.x * blockDim.x + threadIdx.x;
    if (e < E) {
        int pos = atomicAdd(&g_cur[dst[e]], 1);
        g_csr[pos] = src[e];
    } else if (e - E < N_NODES) {
        int i = e - E;
        g_csr[g_off[i + 1] - 1] = i;
    }
}

// ---------------- scalar fp32 GEMM (tail) ----------------
__global__ void k_gemm(const float* __restrict__ A, const float* __restrict__ B,
                       const float* __restrict__ bias, float* __restrict__ C,
                       int M, int N, int K) {
    __shared__ float As[BM][BK];
    __shared__ float Bs[BK][BN + 1];
    int tid = threadIdx.y * 16 + threadIdx.x;
    int m0 = blockIdx.y * BM, n0 = blockIdx.x * BN;
    float acc[4][4] = {};
    for (int k0 = 0; k0 < K; k0 += BK) {
#pragma unroll
        for (int r = 0; r < 4; r++) {
            int e = tid + r * 256;
            int m = e / BK, k = e % BK;
            As[m][k] = (m0 + m < M) ? A[(size_t)(m0 + m) * K + k0 + k] : 0.f;
        }
#pragma unroll
        for (int r = 0; r < 4; r++) {
            int e = tid + r * 256;
            int k = e / BN, n = e % BN;
            Bs[k][n] = (n0 + n < N) ? B[(size_t)(k0 + k) * N + n0 + n] : 0.f;
        }
        __syncthreads();
#pragma unroll
        for (int kk = 0; kk < BK; kk++) {
            float ra[4], rb[4];
#pragma unroll
            for (int i = 0; i < 4; i++) ra[i] = As[threadIdx.y * 4 + i][kk];
#pragma unroll
            for (int j = 0; j < 4; j++) rb[j] = Bs[kk][threadIdx.x * 4 + j];
#pragma unroll
            for (int i = 0; i < 4; i++)
#pragma unroll
                for (int j = 0; j < 4; j++) acc[i][j] += ra[i] * rb[j];
        }
        __syncthreads();
    }
#pragma unroll
    for (int i = 0; i < 4; i++) {
        int m = m0 + threadIdx.y * 4 + i;
        if (m >= M) continue;
#pragma unroll
        for (int j = 0; j < 4; j++) {
            int n = n0 + threadIdx.x * 4 + j;
            if (n >= N) continue;
            float v = acc[i][j];
            if (bias) v += bias[n];
            C[(size_t)m * N + n] = v;
        }
    }
}

__device__ __forceinline__ float leaky(float v) {
    return v > 0.f ? v : NEG_SLOPE * v;
}

__device__ __forceinline__ void fma8(float* acc, uint4 r, float a) {
    const __half2* p = (const __half2*)&r;
#pragma unroll
    for (int j = 0; j < 4; j++) {
        float2 f = __half22float2(p[j]);
        acc[2 * j]     += a * f.x;
        acc[2 * j + 1] += a * f.y;
    }
}

// ---------------- GAT aggregation: warp per node, MLP-8 gather ----------------
__global__ void k_agg(const __half* __restrict__ h, const float* __restrict__ bg,
                      __half* __restrict__ out) {
    int w = (blockIdx.x * blockDim.x + threadIdx.x) >> 5;
    int lane = threadIdx.x & 31;
    if (w >= N_NODES) return;
    int b0 = g_off[w], b1 = g_off[w + 1];
    float edv = g_ed[w];

    // online max+sum, lane-strided
    float m = -1e30f, s = 0.f;
    for (int e = b0 + lane; e < b1; e += 32) {
        float v = leaky(g_es[g_csr[e]] + edv);
        float mn = fmaxf(m, v);
        s = s * __expf(m - mn) + __expf(v - mn);
        m = mn;
    }
#pragma unroll
    for (int o = 16; o; o >>= 1) {
        float mo = __shfl_xor_sync(0xffffffffu, m, o);
        float so = __shfl_xor_sync(0xffffffffu, s, o);
        float mn = fmaxf(m, mo);
        s = s * __expf(m - mn) + so * __expf(mo - mn);
        m = mn;
    }
    float inv = 1.f / (s + EPS_SM);

    // weighted feature sum: 8 edges in flight per iteration
    float acc[8] = {};
    const __half* hl = h + lane * 8;
#pragma unroll 1
    for (int e = b0; e < b1; e += 8) {
        int n = b1 - e;
        int idx[8];
#pragma unroll
        for (int q = 0; q < 8; q++) idx[q] = g_csr[(q < n) ? e + q : e];
        uint4 r[8];
#pragma unroll
        for (int q = 0; q < 8; q++)
            r[q] = *(const uint4*)(hl + (size_t)idx[q] * HIDDEN);
        float al[8];
#pragma unroll
        for (int q = 0; q < 8; q++)
            al[q] = (q < n) ? __expf(leaky(g_es[idx[q]] + edv) - m) * inv : 0.f;
#pragma unroll
        for (int q = 0; q < 8; q++) fma8(acc, r[q], al[q]);
    }

    // +bias, relu, store
    uint4 ov;
    __half2* op = (__half2*)&ov;
#pragma unroll
    for (int j = 0; j < 4; j++) {
        int c = lane * 8 + 2 * j;
        float2 b2 = *(const float2*)(bg + c);
        op[j] = __floats2half2_rn(fmaxf(acc[2 * j] + b2.x, 0.f),
                                  fmaxf(acc[2 * j + 1] + b2.y, 0.f));
    }
    *(uint4*)(out + (size_t)w * HIDDEN + lane * 8) = ov;
}

// ---------------- mean pool ----------------
__global__ void k_pool_zero() {
    int i = blockIdx.x * blockDim.x + threadIdx.x;
    if (i < NUM_GRAPHS * HIDDEN) g_pool[i] = 0.f;
    if (i < NUM_GRAPHS) g_gcnt[i] = 0;
}
__global__ void k_counts(const int* __restrict__ batch) {
    int i = blockIdx.x * blockDim.x + threadIdx.x;
    if (i < N_NODES) atomicAdd(&g_gcnt[batch[i]], 1);
}
__global__ void k_pool(const __half* __restrict__ x, const int* __restrict__ batch) {
    __shared__ int shb[256];
    int c = threadIdx.x;
    int n0 = blockIdx.x * 256;
    shb[c] = batch[n0 + c];
    __syncthreads();
    float acc = 0.f;
    int cg = shb[0];
    for (int n = 0; n < 256; n++) {
        int g = shb[n];
        if (g != cg) {
            atomicAdd(&g_pool[cg * HIDDEN + c], acc);
            acc = 0.f;
            cg = g;
        }
        acc += __half2float(x[(size_t)(n0 + n) * HIDDEN + c]);
    }
    atomicAdd(&g_pool[cg * HIDDEN + c], acc);
}
__global__ void k_mean() {
    int i = blockIdx.x * blockDim.x + threadIdx.x;
    if (i < NUM_GRAPHS * HIDDEN) {
        float cnt = (float)g_gcnt[i >> 8];
        g_pool[i] /= fmaxf(cnt, 1.f);
    }
}

// ---------------- launch ----------------
extern "C" void kernel_launch(void* const* d_in, const int* in_sizes, int n_in,
                              void* d_out, int out_size) {
    const int*   nodes = (const int*)d_in[0];
    const int*   eidx  = (const int*)d_in[1];
    const int*   batch = (const int*)d_in[2];
    const float* emb   = (const float*)d_in[3];
    const float* Wg    = (const float*)d_in[4];
    const float* a_src = (const float*)d_in[5];
    const float* a_dst = (const float*)d_in[6];
    const float* bg    = (const float*)d_in[7];
    const float* Wl    = (const float*)d_in[8];
    const float* bl    = (const float*)d_in[9];
    const float* Wout  = (const float*)d_in[10];
    const float* bout  = (const float*)d_in[11];

    const int E = in_sizes[1] / 2;
    const int* src = eidx;
    const int* dst = eidx + E;

    __half *dx, *dh, *dt, *dWT;
    float *dpool, *des, *ded, *dbc, *dsmall;
    cudaGetSymbolAddress((void**)&dx, g_x);
    cudaGetSymbolAddress((void**)&dh, g_h);
    cudaGetSymbolAddress((void**)&dt, g_t);
    cudaGetSymbolAddress((void**)&dpool, g_pool);
    cudaGetSymbolAddress((void**)&dWT, g_WT);
    cudaGetSymbolAddress((void**)&des, g_es);
    cudaGetSymbolAddress((void**)&ded, g_ed);
    cudaGetSymbolAddress((void**)&dbc, g_bc);
    cudaGetSymbolAddress((void**)&dsmall, g_small);

    cudaFuncSetAttribute(k_gemm_mma, cudaFuncAttributeMaxDynamicSharedMemorySize,
                         SMEM_MMA);

    const int warp_blocks = (N_NODES * 32) / 256;
    const int GRID = N_NODES / 128;
    dim3 blk(16, 16);

    // 1: embed (+deg init)
    k_embed<<<(N_NODES * HIDDEN) / 256, 256>>>(nodes, emb);
    // 2: compose both Wc
    dim3 grd_cmp(HIDDEN / BN, HIDDEN / BM, 2);
    k_compose<<<grd_cmp, blk>>>(Wl, Wg);
    // 3: transposes + composed biases
    k_prep<<<770, 256>>>(Wg, bl);
    // 4: layer-0 GEMM  <-- profiled slot
    k_gemm_mma<<<GRID, 512, SMEM_MMA>>>(dx, dWT, dh, nullptr,
                                        a_src, a_dst, des, ded);
    // 5-7: CSR build
    k_count_deg<<<(E + 255) / 256, 256>>>(dst, E);
    k_scan<<<1, 1024>>>();
    k_fill<<<(E + N_NODES + 255) / 256, 256>>>(src, dst, E);
    // 8: layer-0 aggregation
    k_agg<<<warp_blocks, 256>>>(dh, bg, dt);
    // layer 1
    k_gemm_mma<<<GRID, 512, SMEM_MMA>>>(dt, dWT + HIDDEN * HIDDEN, dh, dbc,
                                        a_src + HIDDEN, a_dst + HIDDEN, des, ded);
    k_agg<<<warp_blocks, 256>>>(dh, bg + HIDDEN, dx);
    // layer 2
    k_gemm_mma<<<GRID, 512, SMEM_MMA>>>(dx, dWT + 2 * HIDDEN * HIDDEN, dh,
                                        dbc + HIDDEN,
                                        a_src + 2 * HIDDEN, a_dst + 2 * HIDDEN,
                                        des, ded);
    k_agg<<<warp_blocks, 256>>>(dh, bg + 2 * HIDDEN, dt);

    // mean pool over t3
    k_pool_zero<<<(NUM_GRAPHS * HIDDEN + 255) / 256, 256>>>();
    k_counts<<<N_NODES / 256, 256>>>(batch);
    k_pool<<<N_NODES / 256, 256>>>(dt, batch);
    k_mean<<<(NUM_GRAPHS * HIDDEN + 255) / 256, 256>>>();

    // small = pooled @ Wl2 + bl2
    dim3 grd_sm(HIDDEN / BN, (NUM_GRAPHS + BM - 1) / BM);
    k_gemm<<<grd_sm, blk>>>(dpool, Wl + 2 * HIDDEN * HIDDEN, bl + 2 * HIDDEN,
                            dsmall, NUM_GRAPHS, HIDDEN, HIDDEN);
    // out = small @ Wout + bout
    dim3 grd_out((VOCAB + BN - 1) / BN, (NUM_GRAPHS + BM - 1) / BM);
    k_gemm<<<grd_out, blk>>>(dsmall, Wout, bout, (float*)d_out,
                             NUM_GRAPHS, VOCAB, HIDDEN);
}